// round 3
// baseline (speedup 1.0000x reference)
#include <cuda_runtime.h>
#include <cuda_fp16.h>
#include <stdint.h>

#define R_NODES   256
#define N_STEPS   512
#define M_SAMP    512
#define OUT_DIM   10
#define LUT_WORDS 8192            // 2^18 bits / 32
#define NPC       8               // samples per CTA
#define N_CTA     (M_SAMP / NPC)  // 64
#define RB_STRIDE 264             // halfs per sample row (pad: 132 words -> conflict-light B loads)

// Scratch: __device__ globals (no allocation allowed)
__device__ unsigned g_lut_bits[R_NODES * LUT_WORDS]; // 8 MB bit-packed LUT
__device__ unsigned g_x_bits[M_SAMP * N_STEPS];      // 1 MB bit-packed inputs (bit i = feature i)

// ---------------------------------------------------------------------------
// Pack LUT: lut int32[256][2^18] (0/1) -> g_lut_bits u32[256][8192]
// bit b of word w (row n) = lut[n][32w + b]
// ---------------------------------------------------------------------------
__global__ void pack_lut_kernel(const int* __restrict__ lut) {
    const int node = blockIdx.x;                 // 256 blocks
    const int wid  = threadIdx.x >> 5;
    const int lane = threadIdx.x & 31;
    const int* src = lut + (size_t)node * (LUT_WORDS * 32);
    unsigned* dst  = g_lut_bits + node * LUT_WORDS;
    const int per_warp = LUT_WORDS / 8;          // 1024 words per warp
    const int w_begin = wid * per_warp;
    for (int w0 = w_begin; w0 < w_begin + per_warp; w0 += 32) {
        unsigned myw = 0;
        #pragma unroll
        for (int i = 0; i < 32; i++) {
            unsigned b = __ballot_sync(0xFFFFFFFFu, src[(size_t)(w0 + i) * 32 + lane] & 1);
            if (i == lane) myw = b;
        }
        dst[w0 + lane] = myw;
    }
}

// ---------------------------------------------------------------------------
// Pack x: int32[512][512][4][8] (0/1) -> g_x_bits[m*512 + t], bit i = feature i (i = d*8+b)
// ---------------------------------------------------------------------------
__global__ void pack_x_kernel(const int* __restrict__ x) {
    int w = blockIdx.x * blockDim.x + threadIdx.x;
    if (w >= M_SAMP * N_STEPS) return;
    const uint4* p = (const uint4*)(x + (size_t)w * 32);   // 32 ints = 8 x uint4
    unsigned word = 0;
    #pragma unroll
    for (int j = 0; j < 8; j++) {
        uint4 v = p[j];
        word |= (v.x & 1u) << (4 * j + 0);
        word |= (v.y & 1u) << (4 * j + 1);
        word |= (v.z & 1u) << (4 * j + 2);
        word |= (v.w & 1u) << (4 * j + 3);
    }
    g_x_bits[w] = word;
}

// ---------------------------------------------------------------------------
// m16n8k16 fp16 MMA, fp32 accumulate (exact: primes <= 1619 exact in fp16,
// per-row sums < 2^18 << 2^24 exact in fp32)
// ---------------------------------------------------------------------------
__device__ __forceinline__ void mma16816(float* d, const unsigned* a, unsigned b0, unsigned b1) {
    asm volatile(
        "mma.sync.aligned.m16n8k16.row.col.f32.f16.f16.f32 "
        "{%0,%1,%2,%3}, {%4,%5,%6,%7}, {%8,%9}, {%0,%1,%2,%3};\n"
        : "+f"(d[0]), "+f"(d[1]), "+f"(d[2]), "+f"(d[3])
        : "r"(a[0]), "r"(a[1]), "r"(a[2]), "r"(a[3]), "r"(b0), "r"(b1));
}

// ---------------------------------------------------------------------------
// Main reservoir kernel: 64 CTAs x 256 threads, CTA b owns samples [8b, 8b+8)
// Warp w owns nodes [32w, 32w+32): A = Wp rows held in 128 registers.
// Per step: 32 HMMA -> idx in accumulators -> bit-packed LUT gather (L2) -> new r in smem.
// ---------------------------------------------------------------------------
__global__ void __launch_bounds__(256, 1)
reservoir_kernel(const int* __restrict__ input_nodes,
                 const int* __restrict__ Wres,
                 const int* __restrict__ primes,
                 const int* __restrict__ init_res,
                 const float* __restrict__ readout_W,
                 const float* __restrict__ readout_b,
                 float* __restrict__ out)
{
    __shared__ __half rbuf[NPC][RB_STRIDE];      // current reservoir state, fp16 0/1
    __shared__ short s_inp[R_NODES];             // node -> input-feature index or -1
    __shared__ int s_innodes[32];                // feature -> node
    __shared__ unsigned short s_ph[R_NODES];     // primes as fp16 bit patterns
    __shared__ float s_W[OUT_DIM * R_NODES];     // readout weights

    const int tid  = threadIdx.x;
    const int wid  = tid >> 5;
    const int lane = tid & 31;
    const int g    = lane >> 2;                  // group id (row within MMA tile)
    const int tg   = lane & 3;                   // thread in group
    const int mbase = blockIdx.x * NPC;
    const __half ONE  = __ushort_as_half(0x3C00);
    const __half ZERO = __ushort_as_half(0x0000);

    // ---- setup shared tables ----
    s_inp[tid] = -1;
    s_ph[tid]  = __half_as_ushort(__int2half_rn(primes[tid]));
    for (int i = tid; i < OUT_DIM * R_NODES; i += 256) s_W[i] = readout_W[i];
    __syncthreads();
    if (tid < 32) {
        int nn = input_nodes[tid];
        s_innodes[tid] = nn;
        s_inp[nn] = (short)tid;
    }

    // ---- fill A fragments (Wp = Wres ? prime : 0), register-resident ----
    unsigned A[16][2][4];
    const int node_base = wid * 32;
    #pragma unroll
    for (int kt = 0; kt < 16; kt++) {
        #pragma unroll
        for (int mt = 0; mt < 2; mt++) {
            #pragma unroll
            for (int r = 0; r < 4; r++) {
                int row = node_base + mt * 16 + g + ((r & 1) ? 8 : 0);
                int k0  = kt * 16 + tg * 2 + ((r & 2) ? 8 : 0);
                unsigned h0 = Wres[row * 256 + k0]     ? (unsigned)s_ph[k0]     : 0u;
                unsigned h1 = Wres[row * 256 + k0 + 1] ? (unsigned)s_ph[k0 + 1] : 0u;
                A[kt][mt][r] = h0 | (h1 << 16);
            }
        }
    }

    // ---- init state: init_res everywhere, then x_0 on input nodes ----
    {
        __half v = init_res[tid] ? ONE : ZERO;
        #pragma unroll
        for (int s = 0; s < NPC; s++) rbuf[s][tid] = v;
    }
    __syncthreads();
    {
        int s = tid >> 5, i = tid & 31;          // warp s = sample s, lane i = feature i
        unsigned xb = (g_x_bits[(mbase + s) * N_STEPS + 0] >> i) & 1u;
        rbuf[s][s_innodes[i]] = xb ? ONE : ZERO;
    }
    __syncthreads();

    // ---- 512 sequential steps ----
    for (int t = 0; t < N_STEPS; t++) {
        float d[2][4];
        #pragma unroll
        for (int mt = 0; mt < 2; mt++)
            #pragma unroll
            for (int e = 0; e < 4; e++) d[mt][e] = 0.0f;

        // idx[node, sample] = Wp . r  (exact)
        #pragma unroll
        for (int kt = 0; kt < 16; kt++) {
            unsigned b0 = *(const unsigned*)&rbuf[g][kt * 16 + tg * 2];
            unsigned b1 = *(const unsigned*)&rbuf[g][kt * 16 + tg * 2 + 8];
            mma16816(d[0], A[kt][0], b0, b1);
            mma16816(d[1], A[kt][1], b0, b1);
        }
        __syncthreads();   // all reads of rbuf complete before writes

        // LUT gather + state write. Input nodes are overwritten by x_{t+1}
        // anyway, so skip their gather except at the final step.
        const bool last = (t == N_STEPS - 1);
        #pragma unroll
        for (int mt = 0; mt < 2; mt++) {
            #pragma unroll
            for (int e = 0; e < 4; e++) {
                int node = node_base + mt * 16 + g + ((e & 2) ? 8 : 0);
                int samp = tg * 2 + (e & 1);
                if (s_inp[node] < 0 || last) {
                    int idx = __float2int_rn(d[mt][e]);
                    unsigned bit = (g_lut_bits[node * LUT_WORDS + (idx >> 5)] >> (idx & 31)) & 1u;
                    rbuf[samp][node] = bit ? ONE : ZERO;
                }
            }
        }

        // Override input nodes with x_{t+1} for the next step
        if (!last) {
            int s = tid >> 5, i = tid & 31;
            unsigned xb = (g_x_bits[(mbase + s) * N_STEPS + t + 1] >> i) & 1u;
            rbuf[s][s_innodes[i]] = xb ? ONE : ZERO;
        }
        __syncthreads();   // writes complete before next step's reads
    }

    // ---- readout: warp w computes outputs for sample w ----
    {
        float acc[OUT_DIM];
        #pragma unroll
        for (int o = 0; o < OUT_DIM; o++) acc[o] = 0.0f;
        #pragma unroll
        for (int kk = 0; kk < 8; kk++) {
            int k = lane + kk * 32;
            float rv = __half2float(rbuf[wid][k]);
            #pragma unroll
            for (int o = 0; o < OUT_DIM; o++)
                acc[o] += rv * s_W[o * R_NODES + k];
        }
        #pragma unroll
        for (int o = 0; o < OUT_DIM; o++) {
            #pragma unroll
            for (int off = 16; off; off >>= 1)
                acc[o] += __shfl_xor_sync(0xFFFFFFFFu, acc[o], off);
        }
        if (lane == 0) {
            #pragma unroll
            for (int o = 0; o < OUT_DIM; o++)
                out[(mbase + wid) * OUT_DIM + o] = acc[o] + readout_b[o];
        }
    }
}

// ---------------------------------------------------------------------------
// kernel_launch. Input order: x, input_nodes, lut, W_res, primes, init_res,
// readout_W, readout_b. bool arrays are delivered as int32.
// ---------------------------------------------------------------------------
extern "C" void kernel_launch(void* const* d_in, const int* in_sizes, int n_in,
                              void* d_out, int out_size) {
    const int*   x        = (const int*)d_in[0];
    const int*   in_nodes = (const int*)d_in[1];
    const int*   lut      = (const int*)d_in[2];
    const int*   Wres     = (const int*)d_in[3];
    const int*   primes   = (const int*)d_in[4];
    const int*   init_res = (const int*)d_in[5];
    const float* rW       = (const float*)d_in[6];
    const float* rb       = (const float*)d_in[7];
    float*       out      = (float*)d_out;

    pack_lut_kernel<<<R_NODES, 256>>>(lut);
    pack_x_kernel<<<(M_SAMP * N_STEPS) / 256, 256>>>(x);
    reservoir_kernel<<<N_CTA, 256>>>(in_nodes, Wres, primes, init_res, rW, rb, out);
}

// round 4
// speedup vs baseline: 1.5944x; 1.5944x over previous
#include <cuda_runtime.h>
#include <cuda_fp16.h>
#include <stdint.h>

#define R_NODES   256
#define N_STEPS   512
#define M_SAMP    512
#define OUT_DIM   10
#define LUT_WORDS 8192            // 2^18 bits / 32
#define NPC       8               // samples per CTA
#define N_CTA     (M_SAMP / NPC)  // 64
#define RB_STRIDE 264             // halfs per row: 132 words, 132%32=4 -> conflict-free B loads

// Scratch: __device__ globals (no allocation allowed)
__device__ unsigned g_lut_bits[R_NODES * LUT_WORDS]; // 8 MB bit-packed LUT
__device__ unsigned g_x_bits[M_SAMP * N_STEPS];      // 1 MB bit-packed inputs

// ---------------------------------------------------------------------------
// Pack LUT (flat): word w of g_lut_bits, bit b = lut[w*32 + b].
// Two-phase per warp: 32 independent LDGs into registers (MLP=32), then 32 ballots.
// Grid: 8192 blocks x 256 threads = 65536 warps, 32 words each.
// ---------------------------------------------------------------------------
__global__ void pack_lut_kernel(const int* __restrict__ lut) {
    const int warp_g = (blockIdx.x * blockDim.x + threadIdx.x) >> 5;
    const int lane   = threadIdx.x & 31;
    const int w0     = warp_g * 32;
    const unsigned* src = (const unsigned*)lut;

    unsigned v[32];
    #pragma unroll
    for (int i = 0; i < 32; i++)
        v[i] = src[(size_t)(w0 + i) * 32 + lane];

    unsigned myw = 0;
    #pragma unroll
    for (int i = 0; i < 32; i++) {
        unsigned b = __ballot_sync(0xFFFFFFFFu, v[i] & 1u);
        if (i == lane) myw = b;
    }
    g_lut_bits[w0 + lane] = myw;
}

// ---------------------------------------------------------------------------
// Pack x: int32[512][512][4][8] (0/1) -> g_x_bits[m*512 + t], bit i = feature i
// ---------------------------------------------------------------------------
__global__ void pack_x_kernel(const int* __restrict__ x) {
    int w = blockIdx.x * blockDim.x + threadIdx.x;
    if (w >= M_SAMP * N_STEPS) return;
    const uint4* p = (const uint4*)(x + (size_t)w * 32);
    unsigned word = 0;
    #pragma unroll
    for (int j = 0; j < 8; j++) {
        uint4 v = p[j];
        word |= (v.x & 1u) << (4 * j + 0);
        word |= (v.y & 1u) << (4 * j + 1);
        word |= (v.z & 1u) << (4 * j + 2);
        word |= (v.w & 1u) << (4 * j + 3);
    }
    g_x_bits[w] = word;
}

// ---------------------------------------------------------------------------
// m16n8k16 fp16 MMA, fp32 accumulate (exact for our integer ranges)
// ---------------------------------------------------------------------------
__device__ __forceinline__ void mma16816(float* d, const unsigned* a, unsigned b0, unsigned b1) {
    asm volatile(
        "mma.sync.aligned.m16n8k16.row.col.f32.f16.f16.f32 "
        "{%0,%1,%2,%3}, {%4,%5,%6,%7}, {%8,%9}, {%0,%1,%2,%3};\n"
        : "+f"(d[0]), "+f"(d[1]), "+f"(d[2]), "+f"(d[3])
        : "r"(a[0]), "r"(a[1]), "r"(a[2]), "r"(a[3]), "r"(b0), "r"(b1));
}

#define MAGIC_F 8388608.0f   // 2^23: final accumulator mantissa low bits == integer index

// ---------------------------------------------------------------------------
// Main reservoir kernel: 64 CTAs x 256 threads, CTA b owns samples [8b, 8b+8)
// Warp w owns nodes [32w, 32w+32): A = Wp rows held in 128 registers.
// Double-buffered state -> one __syncthreads per step.
// 4-way split accumulators -> 4-deep MMA dependency chains.
// ---------------------------------------------------------------------------
__global__ void __launch_bounds__(256, 1)
reservoir_kernel(const int* __restrict__ input_nodes,
                 const int* __restrict__ Wres,
                 const int* __restrict__ primes,
                 const int* __restrict__ init_res,
                 const float* __restrict__ readout_W,
                 const float* __restrict__ readout_b,
                 float* __restrict__ out)
{
    __shared__ __half rb[2][NPC][RB_STRIDE];     // double-buffered state, fp16 0/1
    __shared__ short s_inp[R_NODES];             // node -> input-feature index or -1
    __shared__ int s_innodes[32];                // feature -> node
    __shared__ unsigned short s_ph[R_NODES];     // primes as fp16 bit patterns
    __shared__ float s_W[OUT_DIM * R_NODES];     // readout weights

    const int tid  = threadIdx.x;
    const int wid  = tid >> 5;
    const int lane = tid & 31;
    const int g    = lane >> 2;                  // MMA row-in-tile
    const int tg   = lane & 3;                   // MMA col group
    const int mbase = blockIdx.x * NPC;
    const __half ONE  = __ushort_as_half(0x3C00);
    const __half ZERO = __ushort_as_half(0x0000);

    // ---- shared tables ----
    s_inp[tid] = -1;
    s_ph[tid]  = __half_as_ushort(__int2half_rn(primes[tid]));
    for (int i = tid; i < OUT_DIM * R_NODES; i += 256) s_W[i] = readout_W[i];
    __syncthreads();
    if (tid < 32) {
        int nn = input_nodes[tid];
        s_innodes[tid] = nn;
        s_inp[nn] = (short)tid;
    }

    // ---- A fragments (Wp = Wres ? prime : 0), register-resident ----
    unsigned A[16][2][4];
    const int node_base = wid * 32;
    #pragma unroll
    for (int kt = 0; kt < 16; kt++) {
        #pragma unroll
        for (int mt = 0; mt < 2; mt++) {
            #pragma unroll
            for (int r = 0; r < 4; r++) {
                int row = node_base + mt * 16 + g + ((r & 1) ? 8 : 0);
                int k0  = kt * 16 + tg * 2 + ((r & 2) ? 8 : 0);
                unsigned h0 = Wres[row * 256 + k0]     ? (unsigned)s_ph[k0]     : 0u;
                unsigned h1 = Wres[row * 256 + k0 + 1] ? (unsigned)s_ph[k0 + 1] : 0u;
                A[kt][mt][r] = h0 | (h1 << 16);
            }
        }
    }

    // ---- init state into buffer 0 ----
    {
        __half v = init_res[tid] ? ONE : ZERO;
        #pragma unroll
        for (int s = 0; s < NPC; s++) rb[0][s][tid] = v;
    }
    __syncthreads();
    {
        int s = tid >> 5, i = tid & 31;          // warp s = sample s, lane i = feature i
        unsigned xb = (g_x_bits[(mbase + s) * N_STEPS + 0] >> i) & 1u;
        rb[0][s][s_innodes[i]] = xb ? ONE : ZERO;
    }
    __syncthreads();

    // ---- per-warp gather constants (hoisted out of step loop) ----
    // element (mt, e): node = node_base + mt*16 + g + ((e&2)?8:0); sample = tg*2 + (e&1)
    const unsigned* lp[2][2];                    // [mt][e>>1] LUT row base
    int nodes[2][2];
    bool is_inp[2][2];
    #pragma unroll
    for (int mt = 0; mt < 2; mt++)
        #pragma unroll
        for (int h = 0; h < 2; h++) {
            int n = node_base + mt * 16 + g + h * 8;
            nodes[mt][h]  = n;
            lp[mt][h]     = g_lut_bits + (size_t)n * LUT_WORDS;
            is_inp[mt][h] = (s_inp[n] >= 0);
        }
    const int xs = tid >> 5;                     // this thread's sample for x overwrite
    const int xi = tid & 31;                     // feature index
    const int xnode = s_innodes[xi];
    const unsigned* xrow = g_x_bits + (size_t)(mbase + xs) * N_STEPS;

    // ---- 512 sequential steps, one barrier per step ----
    int p = 0;
    for (int t = 0; t < N_STEPS; t++) {
        const bool last = (t == N_STEPS - 1);
        const __half (*cur)[RB_STRIDE] = rb[p];
        __half (*nxt)[RB_STRIDE] = rb[p ^ 1];

        // prefetch next-step input word (used at step end)
        unsigned xw = 0;
        if (!last) xw = xrow[t + 1];

        // 4-way split accumulators; chunk 0 carries the 2^23 magic offset
        float d[2][4][4];
        #pragma unroll
        for (int mt = 0; mt < 2; mt++)
            #pragma unroll
            for (int c = 0; c < 4; c++)
                #pragma unroll
                for (int e = 0; e < 4; e++)
                    d[mt][c][e] = (c == 0) ? MAGIC_F : 0.0f;

        #pragma unroll
        for (int kt = 0; kt < 16; kt++) {
            unsigned b0 = *(const unsigned*)&cur[g][kt * 16 + tg * 2];
            unsigned b1 = *(const unsigned*)&cur[g][kt * 16 + tg * 2 + 8];
            mma16816(d[0][kt & 3], A[kt][0], b0, b1);
            mma16816(d[1][kt & 3], A[kt][1], b0, b1);
        }

        // indices via magic mantissa trick (exact integer sums)
        unsigned u[2][4];
        #pragma unroll
        for (int mt = 0; mt < 2; mt++)
            #pragma unroll
            for (int e = 0; e < 4; e++) {
                float tot = ((d[mt][0][e] + d[mt][1][e]) + (d[mt][2][e] + d[mt][3][e]));
                u[mt][e] = __float_as_uint(tot) & 0x7FFFFFu;
            }

        // batch the (up to 8) LUT word loads, then extract bits and store
        unsigned w[2][4];
        #pragma unroll
        for (int mt = 0; mt < 2; mt++)
            #pragma unroll
            for (int e = 0; e < 4; e++)
                if (last || !is_inp[mt][e >> 1])
                    w[mt][e] = lp[mt][e >> 1][u[mt][e] >> 5];

        #pragma unroll
        for (int mt = 0; mt < 2; mt++)
            #pragma unroll
            for (int e = 0; e < 4; e++)
                if (last || !is_inp[mt][e >> 1]) {
                    int samp = tg * 2 + (e & 1);
                    nxt[samp][nodes[mt][e >> 1]] =
                        ((w[mt][e] >> (u[mt][e] & 31)) & 1u) ? ONE : ZERO;
                }

        // x_{t+1} into input nodes of the next-state buffer
        if (!last)
            nxt[xs][xnode] = ((xw >> xi) & 1u) ? ONE : ZERO;

        p ^= 1;
        __syncthreads();
    }

    // ---- readout: warp w computes outputs for sample w (final state in rb[0]) ----
    {
        float acc[OUT_DIM];
        #pragma unroll
        for (int o = 0; o < OUT_DIM; o++) acc[o] = 0.0f;
        #pragma unroll
        for (int kk = 0; kk < 8; kk++) {
            int k = lane + kk * 32;
            float rv = __half2float(rb[0][wid][k]);
            #pragma unroll
            for (int o = 0; o < OUT_DIM; o++)
                acc[o] += rv * s_W[o * R_NODES + k];
        }
        #pragma unroll
        for (int o = 0; o < OUT_DIM; o++) {
            #pragma unroll
            for (int off = 16; off; off >>= 1)
                acc[o] += __shfl_xor_sync(0xFFFFFFFFu, acc[o], off);
        }
        if (lane == 0) {
            #pragma unroll
            for (int o = 0; o < OUT_DIM; o++)
                out[(mbase + wid) * OUT_DIM + o] = acc[o] + readout_b[o];
        }
    }
}

// ---------------------------------------------------------------------------
// kernel_launch. Input order: x, input_nodes, lut, W_res, primes, init_res,
// readout_W, readout_b. bool arrays are delivered as int32.
// ---------------------------------------------------------------------------
extern "C" void kernel_launch(void* const* d_in, const int* in_sizes, int n_in,
                              void* d_out, int out_size) {
    const int*   x        = (const int*)d_in[0];
    const int*   in_nodes = (const int*)d_in[1];
    const int*   lut      = (const int*)d_in[2];
    const int*   Wres     = (const int*)d_in[3];
    const int*   primes   = (const int*)d_in[4];
    const int*   init_res = (const int*)d_in[5];
    const float* rW       = (const float*)d_in[6];
    const float* rb       = (const float*)d_in[7];
    float*       out      = (float*)d_out;

    pack_lut_kernel<<<(R_NODES * LUT_WORDS) / (32 * 8), 256>>>(lut);  // 8192 blocks
    pack_x_kernel<<<(M_SAMP * N_STEPS) / 256, 256>>>(x);
    reservoir_kernel<<<N_CTA, 256>>>(in_nodes, Wres, primes, init_res, rW, rb, out);
}